// round 5
// baseline (speedup 1.0000x reference)
#include <cuda_runtime.h>
#include <cstdint>
#include <cstddef>

#define HID   768
#define HID2  1536
#define NLAB  64
#define NTOK  65536          // 16 * 4096
#define KT_SPLITS 12

// Scratch (no allocation allowed): P table and split-K partials for P.
__device__ float g_P[NLAB * HID];
__device__ float g_Pp[KT_SPLITS * NLAB * HID];

__device__ __forceinline__ float to_tf32(float x) {
    uint32_t u;
    asm("cvt.rna.tf32.f32 %0, %1;" : "=r"(u) : "f"(x));
    return __uint_as_float(u);
}

__device__ __forceinline__ void mma_tf32(float d[4], const float a[4], const float b[2]) {
    asm volatile(
        "mma.sync.aligned.m16n8k8.row.col.f32.tf32.tf32.f32 "
        "{%0,%1,%2,%3}, {%4,%5,%6,%7}, {%8,%9}, {%0,%1,%2,%3};\n"
        : "+f"(d[0]), "+f"(d[1]), "+f"(d[2]), "+f"(d[3])
        : "r"(__float_as_uint(a[0])), "r"(__float_as_uint(a[1])),
          "r"(__float_as_uint(a[2])), "r"(__float_as_uint(a[3])),
          "r"(__float_as_uint(b[0])), "r"(__float_as_uint(b[1])));
}

// ---------------------------------------------------------------------------
// P partial: g_Pp[kt][l][j] = sum_{k in kt-chunk} lf[l][k] * W[j][768+k]
// Exact fp32, no atomics (deterministic). grid (6 j-tiles, 12 k-chunks of 64).
// ---------------------------------------------------------------------------
__global__ __launch_bounds__(256) void p_accum_kernel(
        const float* __restrict__ lf, const float* __restrict__ W) {
    __shared__ float lf_s[64][64];     // 16 KB
    __shared__ float w_s[128][33];     // 16.9 KB, padded: conflict-free reads
    const int tid = threadIdx.x;
    const int j0 = blockIdx.x * 128;
    const int k0 = blockIdx.y * 64;

    #pragma unroll
    for (int i = 0; i < 4; i++) {
        int idx = tid + i * 256;
        int r = idx >> 4, c = (idx & 15) * 4;
        *(float4*)&lf_s[r][c] = *(const float4*)(lf + (size_t)r * HID + k0 + c);
    }

    const int jq = tid & 31;     // j = j0 + jq + 32*jj
    const int lq = tid >> 5;     // l = lq*8 + i
    float acc[8][4];
    #pragma unroll
    for (int i = 0; i < 8; i++)
        #pragma unroll
        for (int jj = 0; jj < 4; jj++) acc[i][jj] = 0.f;

    for (int kc = 0; kc < 64; kc += 32) {
        __syncthreads();
        #pragma unroll
        for (int i = 0; i < 4; i++) {
            int idx = tid + i * 256;
            int r = idx >> 3, c = (idx & 7) * 4;
            const float* src = W + (size_t)(j0 + r) * HID2 + HID + k0 + kc + c;
            w_s[r][c] = src[0]; w_s[r][c + 1] = src[1];
            w_s[r][c + 2] = src[2]; w_s[r][c + 3] = src[3];
        }
        __syncthreads();
        #pragma unroll
        for (int kk = 0; kk < 32; kk++) {
            float wv[4], lv[8];
            #pragma unroll
            for (int jj = 0; jj < 4; jj++) wv[jj] = w_s[jq + 32 * jj][kk];
            #pragma unroll
            for (int i = 0; i < 8; i++) lv[i] = lf_s[lq * 8 + i][kc + kk];
            #pragma unroll
            for (int i = 0; i < 8; i++)
                #pragma unroll
                for (int jj = 0; jj < 4; jj++) acc[i][jj] += lv[i] * wv[jj];
        }
    }

    float* dst = g_Pp + (size_t)blockIdx.y * NLAB * HID;
    #pragma unroll
    for (int i = 0; i < 8; i++)
        #pragma unroll
        for (int jj = 0; jj < 4; jj++)
            dst[(size_t)(lq * 8 + i) * HID + j0 + jq + 32 * jj] = acc[i][jj];
}

// g_P[l][j] = bias[j] + sum_kt g_Pp[kt][l][j]   (fixed summation order)
__global__ void p_reduce_kernel(const float* __restrict__ merge_b) {
    int i = blockIdx.x * blockDim.x + threadIdx.x;
    if (i >= NLAB * HID) return;
    float s = merge_b[i % HID];
    #pragma unroll
    for (int t = 0; t < KT_SPLITS; t++) s += g_Pp[t * NLAB * HID + i];
    g_P[i] = s;
}

// ---------------------------------------------------------------------------
// Main fused GEMM: out[n, :] = active ? tokens[n] @ Wl^T + P[label-1] : tokens[n]
// 128x128 tile, BK=32, TF32 mma.sync m16n8k8, 8 warps (2 M x 4 N), 64x32/warp.
// ---------------------------------------------------------------------------
__global__ __launch_bounds__(256, 2) void fm_main_kernel(
        const float* __restrict__ tokens,
        const int* __restrict__ labels,       // int32 (harness canonicalizes int64)
        const float* __restrict__ W,          // left half: row j at W + j*1536
        float* __restrict__ out) {
    __shared__ float As[128][36];   // pad 4: conflict-free frag reads, f4-aligned
    __shared__ float Bs[128][36];
    __shared__ int   s_lbl[128];

    const int tid = threadIdx.x;
    const int m0 = blockIdx.y * 128;
    const int n0 = blockIdx.x * 128;
    if (tid < 128) s_lbl[tid] = labels[m0 + tid];

    const int lane = tid & 31, warp = tid >> 5;
    const int wm = warp >> 2;      // 0..1 -> 64 rows each
    const int wn = warp & 3;       // 0..3 -> 32 cols each

    float acc[4][4][4];
    #pragma unroll
    for (int a = 0; a < 4; a++)
        #pragma unroll
        for (int b = 0; b < 4; b++)
            #pragma unroll
            for (int c = 0; c < 4; c++) acc[a][b][c] = 0.f;

    for (int k0 = 0; k0 < HID; k0 += 32) {
        #pragma unroll
        for (int i = 0; i < 4; i++) {
            int idx = tid + i * 256;
            int r = idx >> 3, c = (idx & 7) * 4;
            float4 va = *(const float4*)(tokens + (size_t)(m0 + r) * HID + k0 + c);
            va.x = to_tf32(va.x); va.y = to_tf32(va.y);
            va.z = to_tf32(va.z); va.w = to_tf32(va.w);
            *(float4*)&As[r][c] = va;
            float4 vb = *(const float4*)(W + (size_t)(n0 + r) * HID2 + k0 + c);
            vb.x = to_tf32(vb.x); vb.y = to_tf32(vb.y);
            vb.z = to_tf32(vb.z); vb.w = to_tf32(vb.w);
            *(float4*)&Bs[r][c] = vb;
        }
        __syncthreads();

        #pragma unroll
        for (int ks = 0; ks < 4; ks++) {
            const int cb = ks * 8 + (lane & 3);
            float a[4][4], b[4][2];
            #pragma unroll
            for (int mi = 0; mi < 4; mi++) {
                int r = wm * 64 + mi * 16 + (lane >> 2);
                a[mi][0] = As[r][cb];     a[mi][1] = As[r + 8][cb];
                a[mi][2] = As[r][cb + 4]; a[mi][3] = As[r + 8][cb + 4];
            }
            #pragma unroll
            for (int ni = 0; ni < 4; ni++) {
                int r = wn * 32 + ni * 8 + (lane >> 2);
                b[ni][0] = Bs[r][cb]; b[ni][1] = Bs[r][cb + 4];
            }
            #pragma unroll
            for (int mi = 0; mi < 4; mi++)
                #pragma unroll
                for (int ni = 0; ni < 4; ni++)
                    mma_tf32(acc[mi][ni], a[mi], b[ni]);
        }
        __syncthreads();
    }

    // Epilogue: += P[label-1] (carries bias) for active rows, else copy token.
    const int gq = lane >> 2, tg = lane & 3;
    #pragma unroll
    for (int mi = 0; mi < 4; mi++) {
        #pragma unroll
        for (int half = 0; half < 2; half++) {
            int r = wm * 64 + mi * 16 + gq + half * 8;
            int lbl = s_lbl[r];
            size_t rowOff = (size_t)(m0 + r) * HID;
            #pragma unroll
            for (int ni = 0; ni < 4; ni++) {
                int gc = n0 + wn * 32 + ni * 8 + tg * 2;
                float2 res;
                if (lbl != 0) {
                    float2 p = *(const float2*)(&g_P[(size_t)(lbl - 1) * HID + gc]);
                    res.x = acc[mi][ni][half * 2 + 0] + p.x;
                    res.y = acc[mi][ni][half * 2 + 1] + p.y;
                } else {
                    res = *(const float2*)(tokens + rowOff + gc);
                }
                *(float2*)(out + rowOff + gc) = res;
            }
        }
    }
}

extern "C" void kernel_launch(void* const* d_in, const int* in_sizes, int n_in,
                              void* d_out, int out_size) {
    const float* com    = (const float*)d_in[0];   // [16,4096,768] f32
    const int*   labels = (const int*)d_in[1];     // [16,4096] (int64 -> int32 by harness)
    const float* lf     = (const float*)d_in[2];   // [64,768] f32
    const float* mw     = (const float*)d_in[3];   // [768,1536] f32
    const float* mb     = (const float*)d_in[4];   // [768] f32
    float* out = (float*)d_out;

    p_accum_kernel<<<dim3(6, KT_SPLITS), 256>>>(lf, mw);
    p_reduce_kernel<<<(NLAB * HID + 255) / 256, 256>>>(mb);
    fm_main_kernel<<<dim3(6, NTOK / 128), 256>>>(com, labels, mw, out);
}

// round 8
// speedup vs baseline: 1.3690x; 1.3690x over previous
#include <cuda_runtime.h>
#include <cuda_bf16.h>
#include <cstdint>
#include <cstddef>

#define HID   768
#define HID2  1536
#define NLAB  64
#define NTOK  65536
#define KT_SPLITS 12

// Arch-specific feature gate: tcgen05 exists only in sm_10Xa-specific passes.
#if defined(__CUDA_ARCH__) && (defined(__CUDA_ARCH_FEAT_SM103_ALL) || \
    defined(__CUDA_ARCH_FEAT_SM100_ALL) || defined(__CUDA_ARCH_SPECIFIC__))
#define USE_TC 1
#else
#define USE_TC 0
#endif

// ---------------- scratch (no allocation allowed) ----------------
__device__ __align__(16) float g_P[NLAB * HID];
__device__ __align__(16) float g_Pp[KT_SPLITS * NLAB * HID];
__device__ __align__(16) __nv_bfloat16 g_Bh[HID * HID];   // hi(W_left), [j][k]
__device__ __align__(16) __nv_bfloat16 g_Bl[HID * HID];   // lo residual

// ---------------- portable helpers ----------------
__device__ __forceinline__ uint32_t smem_u32(const void* p) {
    uint32_t a;
    asm("{ .reg .u64 t; cvta.to.shared.u64 t, %1; cvt.u32.u64 %0, t; }" : "=r"(a) : "l"(p));
    return a;
}
__device__ __forceinline__ float to_tf32(float x) {
    uint32_t u;
    asm("cvt.rna.tf32.f32 %0, %1;" : "=r"(u) : "f"(x));
    return __uint_as_float(u);
}
__device__ __forceinline__ void mma_tf32(float d[4], const float a[4], const float b[2]) {
    asm volatile(
        "mma.sync.aligned.m16n8k8.row.col.f32.tf32.tf32.f32 "
        "{%0,%1,%2,%3}, {%4,%5,%6,%7}, {%8,%9}, {%0,%1,%2,%3};\n"
        : "+f"(d[0]), "+f"(d[1]), "+f"(d[2]), "+f"(d[3])
        : "r"(__float_as_uint(a[0])), "r"(__float_as_uint(a[1])),
          "r"(__float_as_uint(a[2])), "r"(__float_as_uint(a[3])),
          "r"(__float_as_uint(b[0])), "r"(__float_as_uint(b[1])));
}

#define SW128(o) ((o) ^ (((o) >> 3) & 0x70))

// ---------------- sm_103a-specific helpers ----------------
#if USE_TC
__device__ __forceinline__ uint32_t elect_one() {
    uint32_t p;
    asm volatile("{ .reg .pred p; elect.sync _|p, 0xFFFFFFFF; selp.b32 %0, 1, 0, p; }" : "=r"(p));
    return p;
}
#define MBAR_INIT(a, n)  asm volatile("mbarrier.init.shared.b64 [%0], %1;" :: "r"(a), "r"((uint32_t)(n)) : "memory")
#define MBAR_ARRIVE(a)   asm volatile("mbarrier.arrive.shared.b64 _, [%0];" :: "r"(a) : "memory")
#define MBAR_WAIT(a, ph) do {                                                      \
    uint32_t _m = (a), _p = (ph), _d;                                              \
    asm volatile("{ .reg .pred p; mbarrier.try_wait.parity.acquire.cta.shared::cta.b64 p, [%1], %2; selp.b32 %0,1,0,p; }" \
        : "=r"(_d) : "r"(_m), "r"(_p) : "memory");                                 \
    if (!_d) {                                                                     \
        asm volatile("{ .reg .pred P1; WL_%=: mbarrier.try_wait.parity.acquire.cta.shared::cta.b64 P1, [%0], %1, 0x989680;" \
                     " @P1 bra.uni WD_%=; bra.uni WL_%=; WD_%=: }"                 \
                     :: "r"(_m), "r"(_p) : "memory");                              \
    } } while (0)
#define TC_ALLOC(sa, n)   asm volatile("tcgen05.alloc.cta_group::1.sync.aligned.shared::cta.b32 [%0], %1;" :: "r"(sa), "r"((uint32_t)(n)) : "memory")
#define TC_DEALLOC(t, n)  asm volatile("tcgen05.dealloc.cta_group::1.sync.aligned.b32 %0, %1;" :: "r"(t), "r"((uint32_t)(n)))
#define TC_RELINQ()       asm volatile("tcgen05.relinquish_alloc_permit.cta_group::1.sync.aligned;")
#define TC_COMMIT(a)      asm volatile("tcgen05.commit.cta_group::1.mbarrier::arrive::one.shared::cluster.b64 [%0];" :: "r"(a) : "memory")
#define TC_WAIT_LD()      asm volatile("tcgen05.wait::ld.sync.aligned;" ::: "memory")
#define TC_FENCE_AFTER()  asm volatile("tcgen05.fence::after_thread_sync;" ::: "memory")
#define FENCE_ASYNC()     asm volatile("fence.proxy.async.shared::cta;" ::: "memory")
#define LDTM_X32(r, t) \
    asm volatile("tcgen05.ld.sync.aligned.32x32b.x32.b32 " \
        "{%0,%1,%2,%3,%4,%5,%6,%7,%8,%9,%10,%11,%12,%13,%14,%15," \
        "%16,%17,%18,%19,%20,%21,%22,%23,%24,%25,%26,%27,%28,%29,%30,%31}, [%32];" \
        : "=r"((r)[0]),"=r"((r)[1]),"=r"((r)[2]),"=r"((r)[3]),"=r"((r)[4]),"=r"((r)[5]),"=r"((r)[6]),"=r"((r)[7]), \
          "=r"((r)[8]),"=r"((r)[9]),"=r"((r)[10]),"=r"((r)[11]),"=r"((r)[12]),"=r"((r)[13]),"=r"((r)[14]),"=r"((r)[15]), \
          "=r"((r)[16]),"=r"((r)[17]),"=r"((r)[18]),"=r"((r)[19]),"=r"((r)[20]),"=r"((r)[21]),"=r"((r)[22]),"=r"((r)[23]), \
          "=r"((r)[24]),"=r"((r)[25]),"=r"((r)[26]),"=r"((r)[27]),"=r"((r)[28]),"=r"((r)[29]),"=r"((r)[30]),"=r"((r)[31]) \
        : "r"(t))

static constexpr uint64_t DESC_BASE_SW128 =
    (uint64_t(2) << 61) | (uint64_t(1) << 46) | (uint64_t(64) << 32) | (uint64_t(1) << 16);
#define MK_DESC(a) (DESC_BASE_SW128 | ((uint64_t)((a) >> 4) & 0x3FFF))

// idesc kind::f16: dtype F32 @4, atype BF16 @7, btype BF16 @10, N>>3 @17, M>>4 @24
static constexpr uint32_t IDESC_128x128 =
    (1u << 4) | (1u << 7) | (1u << 10) | ((128u / 8) << 17) | ((128u / 16) << 24);

__device__ __forceinline__ void mma_bf16_ss(uint32_t d_tmem, uint64_t a_desc,
                                            uint64_t b_desc, uint32_t en) {
    asm volatile(
        "{ .reg .pred p; setp.ne.u32 p, %4, 0;"
        " tcgen05.mma.cta_group::1.kind::f16 [%0], %1, %2, %3, {%5,%5,%5,%5}, p; }"
        :: "r"(d_tmem), "l"(a_desc), "l"(b_desc), "r"(IDESC_128x128),
           "r"(en), "r"(0u) : "memory");
}
#endif // USE_TC

// ---------------- prep: split W_left into bf16 hi/lo ----------------
__global__ void bsplit_kernel(const float* __restrict__ W) {
    int n = blockIdx.x * 256 + threadIdx.x;      // 768*192
    int j = n / 192, k4 = (n % 192) * 4;
    float4 v = *(const float4*)(W + (size_t)j * HID2 + k4);
    __nv_bfloat16 hx = __float2bfloat16(v.x), hy = __float2bfloat16(v.y);
    __nv_bfloat16 hz = __float2bfloat16(v.z), hw = __float2bfloat16(v.w);
    __nv_bfloat162 h0 = {hx, hy}, h1 = {hz, hw};
    __nv_bfloat162 l0 = {__float2bfloat16(v.x - __bfloat162float(hx)),
                         __float2bfloat16(v.y - __bfloat162float(hy))};
    __nv_bfloat162 l1 = {__float2bfloat16(v.z - __bfloat162float(hz)),
                         __float2bfloat16(v.w - __bfloat162float(hw))};
    size_t o = (size_t)j * HID + k4;
    *(uint2*)(g_Bh + o) = make_uint2(*(uint32_t*)&h0, *(uint32_t*)&h1);
    *(uint2*)(g_Bl + o) = make_uint2(*(uint32_t*)&l0, *(uint32_t*)&l1);
}

// ---------------- P table (exact fp32, deterministic) ----------------
__global__ __launch_bounds__(256) void p_accum_kernel(
        const float* __restrict__ lf, const float* __restrict__ W) {
    __shared__ float lf_s[64][64];
    __shared__ float w_s[128][33];
    const int tid = threadIdx.x;
    const int j0 = blockIdx.x * 128, k0 = blockIdx.y * 64;
    #pragma unroll
    for (int i = 0; i < 4; i++) {
        int idx = tid + i * 256, r = idx >> 4, c = (idx & 15) * 4;
        *(float4*)&lf_s[r][c] = *(const float4*)(lf + (size_t)r * HID + k0 + c);
    }
    const int jq = tid & 31, lq = tid >> 5;
    float acc[8][4];
    #pragma unroll
    for (int i = 0; i < 8; i++)
        #pragma unroll
        for (int jj = 0; jj < 4; jj++) acc[i][jj] = 0.f;
    for (int kc = 0; kc < 64; kc += 32) {
        __syncthreads();
        #pragma unroll
        for (int i = 0; i < 4; i++) {
            int idx = tid + i * 256, r = idx >> 3, c = (idx & 7) * 4;
            const float* src = W + (size_t)(j0 + r) * HID2 + HID + k0 + kc + c;
            w_s[r][c] = src[0]; w_s[r][c+1] = src[1]; w_s[r][c+2] = src[2]; w_s[r][c+3] = src[3];
        }
        __syncthreads();
        #pragma unroll
        for (int kk = 0; kk < 32; kk++) {
            float wv[4], lv[8];
            #pragma unroll
            for (int jj = 0; jj < 4; jj++) wv[jj] = w_s[jq + 32 * jj][kk];
            #pragma unroll
            for (int i = 0; i < 8; i++) lv[i] = lf_s[lq * 8 + i][kc + kk];
            #pragma unroll
            for (int i = 0; i < 8; i++)
                #pragma unroll
                for (int jj = 0; jj < 4; jj++) acc[i][jj] += lv[i] * wv[jj];
        }
    }
    float* dst = g_Pp + (size_t)blockIdx.y * NLAB * HID;
    #pragma unroll
    for (int i = 0; i < 8; i++)
        #pragma unroll
        for (int jj = 0; jj < 4; jj++)
            dst[(size_t)(lq * 8 + i) * HID + j0 + jq + 32 * jj] = acc[i][jj];
}

__global__ void p_reduce_kernel(const float* __restrict__ merge_b) {
    int i = blockIdx.x * blockDim.x + threadIdx.x;
    if (i >= NLAB * HID) return;
    float s = merge_b[i % HID];
    #pragma unroll
    for (int t = 0; t < KT_SPLITS; t++) s += g_Pp[t * NLAB * HID + i];
    g_P[i] = s;
}

// ---------------------------------------------------------------------------
// Main kernel, one symbol, two compile-time bodies:
//  USE_TC: tcgen05 SS bf16 hi/lo (3-term), warp-specialized, 2-stage pipeline.
//  else:   proven TF32 mma.sync path (round-5), adapted to 288 thr / dyn smem.
// ---------------------------------------------------------------------------
#define STG_BYTES 65536               // Ah|Al|Bh|Bl 16KB each
#define OFF_AH(s) (1024 + (s) * STG_BYTES)
#define OFF_AL(s) (OFF_AH(s) + 16384)
#define OFF_BH(s) (OFF_AH(s) + 32768)
#define OFF_BL(s) (OFF_AH(s) + 49152)
#define SMEM_TOTAL (1024 + 2 * STG_BYTES)
#define MB_FULL(s)  (sb + 16 + (s) * 8)
#define MB_EMPTY(s) (sb + 32 + (s) * 8)
#define MB_DONE     (sb + 48)

__global__ __launch_bounds__(288, 1)
void fm_main_kernel(const float* __restrict__ tokens,
                    const int* __restrict__ labels,
                    const float* __restrict__ W,
                    float* __restrict__ out) {
    extern __shared__ char smem[];
    const int tid = threadIdx.x, wid = tid >> 5, lane = tid & 31;
    const int m0 = blockIdx.y * 128, n0 = blockIdx.x * 128;

#if USE_TC
    const uint32_t sb = smem_u32(smem);
    int* lbl_s = (int*)(smem + 64);
    if (tid < 128) lbl_s[tid] = labels[m0 + tid];
    if (tid == 0) {
        MBAR_INIT(MB_FULL(0), 256); MBAR_INIT(MB_FULL(1), 256);
        MBAR_INIT(MB_EMPTY(0), 1);  MBAR_INIT(MB_EMPTY(1), 1);
        MBAR_INIT(MB_DONE, 1);
    }
    if (wid == 8) { TC_ALLOC(sb, 128); TC_RELINQ(); }
    __syncthreads();
    uint32_t tmem;
    asm volatile("ld.shared.b32 %0, [%1];" : "=r"(tmem) : "r"(sb));

    if (wid == 8) {
        // ---- MMA issuer warp ----
        for (int c = 0; c < 12; c++) {
            const int s = c & 1;
            MBAR_WAIT(MB_FULL(s), (c >> 1) & 1);
            if (elect_one()) {
                uint64_t ah = MK_DESC(sb + OFF_AH(s)), al = MK_DESC(sb + OFF_AL(s));
                uint64_t bh = MK_DESC(sb + OFF_BH(s)), bl = MK_DESC(sb + OFF_BL(s));
                #pragma unroll
                for (int ks = 0; ks < 4; ks++) {
                    mma_bf16_ss(tmem, ah + 2 * ks, bh + 2 * ks, (c | ks) ? 1u : 0u);
                    mma_bf16_ss(tmem, ah + 2 * ks, bl + 2 * ks, 1u);
                    mma_bf16_ss(tmem, al + 2 * ks, bh + 2 * ks, 1u);
                }
                TC_COMMIT(MB_EMPTY(s));
                if (c == 11) TC_COMMIT(MB_DONE);
            }
        }
    } else {
        // ---- producers: 256 threads, half-row (32 k) each ----
        const int r = tid >> 1, kh = (tid & 1) * 32;
        const float* arow = tokens + (size_t)(m0 + r) * HID + kh;
        const __nv_bfloat16* bhrow = g_Bh + (size_t)(n0 + r) * HID + kh;
        const __nv_bfloat16* blrow = g_Bl + (size_t)(n0 + r) * HID + kh;
        uint32_t swo[4];
        #pragma unroll
        for (int u = 0; u < 4; u++) swo[u] = SW128((uint32_t)(r * 128 + (kh + 8 * u) * 2));

        for (int c = 0; c < 12; c++) {
            const int s = c & 1, k0 = c * 64;
            if (c >= 2) MBAR_WAIT(MB_EMPTY(s), ((c >> 1) - 1) & 1);
            uint32_t h[16], l[16];
            #pragma unroll
            for (int i = 0; i < 8; i++) {
                float4 v = *(const float4*)(arow + k0 + 4 * i);
                __nv_bfloat16 hx = __float2bfloat16(v.x), hy = __float2bfloat16(v.y);
                __nv_bfloat16 hz = __float2bfloat16(v.z), hw = __float2bfloat16(v.w);
                __nv_bfloat162 p0 = {hx, hy}, p1 = {hz, hw};
                h[2 * i] = *(uint32_t*)&p0; h[2 * i + 1] = *(uint32_t*)&p1;
                __nv_bfloat162 q0 = {__float2bfloat16(v.x - __bfloat162float(hx)),
                                     __float2bfloat16(v.y - __bfloat162float(hy))};
                __nv_bfloat162 q1 = {__float2bfloat16(v.z - __bfloat162float(hz)),
                                     __float2bfloat16(v.w - __bfloat162float(hw))};
                l[2 * i] = *(uint32_t*)&q0; l[2 * i + 1] = *(uint32_t*)&q1;
            }
            #pragma unroll
            for (int u = 0; u < 4; u++) {
                *(uint4*)(smem + OFF_AH(s) + swo[u]) =
                    make_uint4(h[4*u], h[4*u+1], h[4*u+2], h[4*u+3]);
                *(uint4*)(smem + OFF_AL(s) + swo[u]) =
                    make_uint4(l[4*u], l[4*u+1], l[4*u+2], l[4*u+3]);
                *(uint4*)(smem + OFF_BH(s) + swo[u]) = *(const uint4*)(bhrow + k0 + 8 * u);
                *(uint4*)(smem + OFF_BL(s) + swo[u]) = *(const uint4*)(blrow + k0 + 8 * u);
            }
            FENCE_ASYNC();
            MBAR_ARRIVE(MB_FULL(s));
        }
    }

    // ---- epilogue: TMEM -> SMEM transpose -> coalesced STG ----
    MBAR_WAIT(MB_DONE, 0);
    TC_FENCE_AFTER();
    float* eps = (float*)(smem + 1024);          // [128][65]
    #pragma unroll
    for (int h = 0; h < 2; h++) {
        if (wid < 4) {
            uint32_t d[64];
            LDTM_X32(d, tmem + h * 64);
            LDTM_X32(d + 32, tmem + h * 64 + 32);
            TC_WAIT_LD();
            const int row = wid * 32 + lane;
            #pragma unroll
            for (int cc = 0; cc < 64; cc++) eps[row * 65 + cc] = __uint_as_float(d[cc]);
        }
        __syncthreads();
        if (tid < 256) {
            const int r = tid >> 1, cb = (tid & 1) * 32;
            const int lbl = lbl_s[r];
            const size_t ro = (size_t)(m0 + r) * HID + n0 + h * 64 + cb;
            if (lbl) {
                const float* prow = g_P + (size_t)(lbl - 1) * HID + n0 + h * 64 + cb;
                #pragma unroll
                for (int q = 0; q < 8; q++) {
                    float4 o;
                    o.x = eps[r * 65 + cb + 4*q + 0] + prow[4*q + 0];
                    o.y = eps[r * 65 + cb + 4*q + 1] + prow[4*q + 1];
                    o.z = eps[r * 65 + cb + 4*q + 2] + prow[4*q + 2];
                    o.w = eps[r * 65 + cb + 4*q + 3] + prow[4*q + 3];
                    *(float4*)(out + ro + 4*q) = o;
                }
            } else {
                #pragma unroll
                for (int q = 0; q < 8; q++)
                    *(float4*)(out + ro + 4*q) = *(const float4*)(tokens + ro + 4*q);
            }
        }
        __syncthreads();
    }
    if (wid == 8) TC_DEALLOC(tmem, 128);

#else  // ------------------- portable TF32 mma.sync fallback -------------------
    float (*As)[36] = (float(*)[36])(smem);                  // [128][36]
    float (*Bs)[36] = (float(*)[36])(smem + 128 * 36 * 4);   // [128][36]
    int*   lbl_s    = (int*)(smem + 2 * 128 * 36 * 4);

    if (tid < 128) lbl_s[tid] = labels[m0 + tid];

    const int wm = wid >> 2, wn = wid & 3;   // valid for wid<8 only
    float acc[4][4][4];
    #pragma unroll
    for (int a = 0; a < 4; a++)
        #pragma unroll
        for (int b = 0; b < 4; b++)
            #pragma unroll
            for (int c = 0; c < 4; c++) acc[a][b][c] = 0.f;

    for (int k0 = 0; k0 < HID; k0 += 32) {
        if (tid < 256) {
            #pragma unroll
            for (int i = 0; i < 4; i++) {
                int idx = tid + i * 256;
                int r = idx >> 3, c = (idx & 7) * 4;
                float4 va = *(const float4*)(tokens + (size_t)(m0 + r) * HID + k0 + c);
                va.x = to_tf32(va.x); va.y = to_tf32(va.y);
                va.z = to_tf32(va.z); va.w = to_tf32(va.w);
                *(float4*)&As[r][c] = va;
                float4 vb = *(const float4*)(W + (size_t)(n0 + r) * HID2 + k0 + c);
                vb.x = to_tf32(vb.x); vb.y = to_tf32(vb.y);
                vb.z = to_tf32(vb.z); vb.w = to_tf32(vb.w);
                *(float4*)&Bs[r][c] = vb;
            }
        }
        __syncthreads();
        if (tid < 256) {
            #pragma unroll
            for (int ks = 0; ks < 4; ks++) {
                const int cb = ks * 8 + (lane & 3);
                float a[4][4], b[4][2];
                #pragma unroll
                for (int mi = 0; mi < 4; mi++) {
                    int r = wm * 64 + mi * 16 + (lane >> 2);
                    a[mi][0] = As[r][cb];     a[mi][1] = As[r + 8][cb];
                    a[mi][2] = As[r][cb + 4]; a[mi][3] = As[r + 8][cb + 4];
                }
                #pragma unroll
                for (int ni = 0; ni < 4; ni++) {
                    int r = wn * 32 + ni * 8 + (lane >> 2);
                    b[ni][0] = Bs[r][cb]; b[ni][1] = Bs[r][cb + 4];
                }
                #pragma unroll
                for (int mi = 0; mi < 4; mi++)
                    #pragma unroll
                    for (int ni = 0; ni < 4; ni++)
                        mma_tf32(acc[mi][ni], a[mi], b[ni]);
            }
        }
        __syncthreads();
    }

    if (tid < 256) {
        const int gq = lane >> 2, tg = lane & 3;
        #pragma unroll
        for (int mi = 0; mi < 4; mi++) {
            #pragma unroll
            for (int half = 0; half < 2; half++) {
                int r = wm * 64 + mi * 16 + gq + half * 8;
                int lbl = lbl_s[r];
                size_t rowOff = (size_t)(m0 + r) * HID;
                #pragma unroll
                for (int ni = 0; ni < 4; ni++) {
                    int gc = n0 + wn * 32 + ni * 8 + tg * 2;
                    float2 res;
                    if (lbl != 0) {
                        float2 p = *(const float2*)(&g_P[(size_t)(lbl - 1) * HID + gc]);
                        res.x = acc[mi][ni][half * 2 + 0] + p.x;
                        res.y = acc[mi][ni][half * 2 + 1] + p.y;
                    } else {
                        res = *(const float2*)(tokens + rowOff + gc);
                    }
                    *(float2*)(out + rowOff + gc) = res;
                }
            }
        }
    }
#endif
}

extern "C" void kernel_launch(void* const* d_in, const int* in_sizes, int n_in,
                              void* d_out, int out_size) {
    const float* com    = (const float*)d_in[0];   // [16,4096,768] f32
    const int*   labels = (const int*)d_in[1];     // [16,4096] int32
    const float* lf     = (const float*)d_in[2];   // [64,768] f32
    const float* mw     = (const float*)d_in[3];   // [768,1536] f32
    const float* mb     = (const float*)d_in[4];   // [768] f32
    float* out = (float*)d_out;

    cudaFuncSetAttribute(fm_main_kernel,
                         cudaFuncAttributeMaxDynamicSharedMemorySize, SMEM_TOTAL);

    bsplit_kernel<<<576, 256>>>(mw);
    p_accum_kernel<<<dim3(6, KT_SPLITS), 256>>>(lf, mw);
    p_reduce_kernel<<<(NLAB * HID + 255) / 256, 256>>>(mb);
    fm_main_kernel<<<dim3(6, NTOK / 128), 288, SMEM_TOTAL>>>(com, labels, mw, out);
}

// round 11
// speedup vs baseline: 1.6482x; 1.2039x over previous
#include <cuda_runtime.h>
#include <cuda_bf16.h>
#include <cstdint>
#include <cstddef>

#define HID   768
#define HID2  1536
#define NLAB  64
#define NTOK  65536
#define KT_SPLITS 12

// Arch-specific feature gate: tcgen05 exists only in sm_10Xa-specific passes.
#if defined(__CUDA_ARCH__) && (defined(__CUDA_ARCH_FEAT_SM103_ALL) || \
    defined(__CUDA_ARCH_FEAT_SM100_ALL) || defined(__CUDA_ARCH_SPECIFIC__))
#define USE_TC 1
#else
#define USE_TC 0
#endif

// ---------------- scratch (no allocation allowed) ----------------
__device__ __align__(16) float g_P[NLAB * HID];
__device__ __align__(16) float g_Pp[KT_SPLITS * NLAB * HID];
__device__ __align__(16) __nv_bfloat16 g_Bh[HID * HID];   // hi(W_left), [j][k]
__device__ __align__(16) __nv_bfloat16 g_Bl[HID * HID];   // lo residual

// ---------------- portable helpers ----------------
__device__ __forceinline__ uint32_t smem_u32(const void* p) {
    uint32_t a;
    asm("{ .reg .u64 t; cvta.to.shared.u64 t, %1; cvt.u32.u64 %0, t; }" : "=r"(a) : "l"(p));
    return a;
}
__device__ __forceinline__ float to_tf32(float x) {
    uint32_t u;
    asm("cvt.rna.tf32.f32 %0, %1;" : "=r"(u) : "f"(x));
    return __uint_as_float(u);
}
__device__ __forceinline__ void mma_tf32(float d[4], const float a[4], const float b[2]) {
    asm volatile(
        "mma.sync.aligned.m16n8k8.row.col.f32.tf32.tf32.f32 "
        "{%0,%1,%2,%3}, {%4,%5,%6,%7}, {%8,%9}, {%0,%1,%2,%3};\n"
        : "+f"(d[0]), "+f"(d[1]), "+f"(d[2]), "+f"(d[3])
        : "r"(__float_as_uint(a[0])), "r"(__float_as_uint(a[1])),
          "r"(__float_as_uint(a[2])), "r"(__float_as_uint(a[3])),
          "r"(__float_as_uint(b[0])), "r"(__float_as_uint(b[1])));
}

#define SW128(o) ((o) ^ (((o) >> 3) & 0x70))

// cp.async (Ampere+, portable): 16B, .cg = L1-bypass
#define CP_ASYNC16(dst, src) \
    asm volatile("cp.async.cg.shared.global [%0], [%1], 16;" :: "r"(dst), "l"(src) : "memory")
#define CP_COMMIT() asm volatile("cp.async.commit_group;" ::: "memory")
#define CP_WAIT0()  asm volatile("cp.async.wait_group 0;" ::: "memory")

// ---------------- sm_103a-specific helpers ----------------
#if USE_TC
__device__ __forceinline__ uint32_t elect_one() {
    uint32_t p;
    asm volatile("{ .reg .pred p; elect.sync _|p, 0xFFFFFFFF; selp.b32 %0, 1, 0, p; }" : "=r"(p));
    return p;
}
#define MBAR_INIT(a, n)  asm volatile("mbarrier.init.shared.b64 [%0], %1;" :: "r"(a), "r"((uint32_t)(n)) : "memory")
#define MBAR_ARRIVE(a)   asm volatile("mbarrier.arrive.shared.b64 _, [%0];" :: "r"(a) : "memory")
#define MBAR_WAIT(a, ph) do {                                                      \
    uint32_t _m = (a), _p = (ph), _d;                                              \
    asm volatile("{ .reg .pred p; mbarrier.try_wait.parity.acquire.cta.shared::cta.b64 p, [%1], %2; selp.b32 %0,1,0,p; }" \
        : "=r"(_d) : "r"(_m), "r"(_p) : "memory");                                 \
    if (!_d) {                                                                     \
        asm volatile("{ .reg .pred P1; WL_%=: mbarrier.try_wait.parity.acquire.cta.shared::cta.b64 P1, [%0], %1, 0x989680;" \
                     " @P1 bra.uni WD_%=; bra.uni WL_%=; WD_%=: }"                 \
                     :: "r"(_m), "r"(_p) : "memory");                              \
    } } while (0)
#define TC_ALLOC(sa, n)   asm volatile("tcgen05.alloc.cta_group::1.sync.aligned.shared::cta.b32 [%0], %1;" :: "r"(sa), "r"((uint32_t)(n)) : "memory")
#define TC_DEALLOC(t, n)  asm volatile("tcgen05.dealloc.cta_group::1.sync.aligned.b32 %0, %1;" :: "r"(t), "r"((uint32_t)(n)))
#define TC_RELINQ()       asm volatile("tcgen05.relinquish_alloc_permit.cta_group::1.sync.aligned;")
#define TC_COMMIT(a)      asm volatile("tcgen05.commit.cta_group::1.mbarrier::arrive::one.shared::cluster.b64 [%0];" :: "r"(a) : "memory")
#define TC_WAIT_LD()      asm volatile("tcgen05.wait::ld.sync.aligned;" ::: "memory")
#define TC_FENCE_AFTER()  asm volatile("tcgen05.fence::after_thread_sync;" ::: "memory")
#define FENCE_ASYNC()     asm volatile("fence.proxy.async.shared::cta;" ::: "memory")
#define LDTM_X32(r, t) \
    asm volatile("tcgen05.ld.sync.aligned.32x32b.x32.b32 " \
        "{%0,%1,%2,%3,%4,%5,%6,%7,%8,%9,%10,%11,%12,%13,%14,%15," \
        "%16,%17,%18,%19,%20,%21,%22,%23,%24,%25,%26,%27,%28,%29,%30,%31}, [%32];" \
        : "=r"((r)[0]),"=r"((r)[1]),"=r"((r)[2]),"=r"((r)[3]),"=r"((r)[4]),"=r"((r)[5]),"=r"((r)[6]),"=r"((r)[7]), \
          "=r"((r)[8]),"=r"((r)[9]),"=r"((r)[10]),"=r"((r)[11]),"=r"((r)[12]),"=r"((r)[13]),"=r"((r)[14]),"=r"((r)[15]), \
          "=r"((r)[16]),"=r"((r)[17]),"=r"((r)[18]),"=r"((r)[19]),"=r"((r)[20]),"=r"((r)[21]),"=r"((r)[22]),"=r"((r)[23]), \
          "=r"((r)[24]),"=r"((r)[25]),"=r"((r)[26]),"=r"((r)[27]),"=r"((r)[28]),"=r"((r)[29]),"=r"((r)[30]),"=r"((r)[31]) \
        : "r"(t))

static constexpr uint64_t DESC_BASE_SW128 =
    (uint64_t(2) << 61) | (uint64_t(1) << 46) | (uint64_t(64) << 32) | (uint64_t(1) << 16);
#define MK_DESC(a) (DESC_BASE_SW128 | ((uint64_t)((a) >> 4) & 0x3FFF))

// idesc kind::f16: dtype F32 @4, atype BF16 @7, btype BF16 @10, N>>3 @17, M>>4 @24
static constexpr uint32_t IDESC_128x256 =
    (1u << 4) | (1u << 7) | (1u << 10) | ((256u / 8) << 17) | ((128u / 16) << 24);

__device__ __forceinline__ void mma_bf16_ss(uint32_t d_tmem, uint64_t a_desc,
                                            uint64_t b_desc, uint32_t en) {
    asm volatile(
        "{ .reg .pred p; setp.ne.u32 p, %4, 0;"
        " tcgen05.mma.cta_group::1.kind::f16 [%0], %1, %2, %3, {%5,%5,%5,%5}, p; }"
        :: "r"(d_tmem), "l"(a_desc), "l"(b_desc), "r"(IDESC_128x256),
           "r"(en), "r"(0u) : "memory");
}
#endif // USE_TC

// ---------------- prep: split W_left into bf16 hi/lo ----------------
__global__ void bsplit_kernel(const float* __restrict__ W) {
    int n = blockIdx.x * 256 + threadIdx.x;      // 768*192
    int j = n / 192, k4 = (n % 192) * 4;
    float4 v = *(const float4*)(W + (size_t)j * HID2 + k4);
    __nv_bfloat16 hx = __float2bfloat16(v.x), hy = __float2bfloat16(v.y);
    __nv_bfloat16 hz = __float2bfloat16(v.z), hw = __float2bfloat16(v.w);
    __nv_bfloat162 h0 = {hx, hy}, h1 = {hz, hw};
    __nv_bfloat162 l0 = {__float2bfloat16(v.x - __bfloat162float(hx)),
                         __float2bfloat16(v.y - __bfloat162float(hy))};
    __nv_bfloat162 l1 = {__float2bfloat16(v.z - __bfloat162float(hz)),
                         __float2bfloat16(v.w - __bfloat162float(hw))};
    size_t o = (size_t)j * HID + k4;
    *(uint2*)(g_Bh + o) = make_uint2(*(uint32_t*)&h0, *(uint32_t*)&h1);
    *(uint2*)(g_Bl + o) = make_uint2(*(uint32_t*)&l0, *(uint32_t*)&l1);
}

// ---------------- P table (exact fp32, deterministic) ----------------
__global__ __launch_bounds__(256) void p_accum_kernel(
        const float* __restrict__ lf, const float* __restrict__ W) {
    __shared__ float lf_s[64][64];
    __shared__ float w_s[128][33];
    const int tid = threadIdx.x;
    const int j0 = blockIdx.x * 128, k0 = blockIdx.y * 64;
    #pragma unroll
    for (int i = 0; i < 4; i++) {
        int idx = tid + i * 256, r = idx >> 4, c = (idx & 15) * 4;
        *(float4*)&lf_s[r][c] = *(const float4*)(lf + (size_t)r * HID + k0 + c);
    }
    const int jq = tid & 31, lq = tid >> 5;
    float acc[8][4];
    #pragma unroll
    for (int i = 0; i < 8; i++)
        #pragma unroll
        for (int jj = 0; jj < 4; jj++) acc[i][jj] = 0.f;
    for (int kc = 0; kc < 64; kc += 32) {
        __syncthreads();
        #pragma unroll
        for (int i = 0; i < 4; i++) {
            int idx = tid + i * 256, r = idx >> 3, c = (idx & 7) * 4;
            const float* src = W + (size_t)(j0 + r) * HID2 + HID + k0 + kc + c;
            w_s[r][c] = src[0]; w_s[r][c+1] = src[1]; w_s[r][c+2] = src[2]; w_s[r][c+3] = src[3];
        }
        __syncthreads();
        #pragma unroll
        for (int kk = 0; kk < 32; kk++) {
            float wv[4], lv[8];
            #pragma unroll
            for (int jj = 0; jj < 4; jj++) wv[jj] = w_s[jq + 32 * jj][kk];
            #pragma unroll
            for (int i = 0; i < 8; i++) lv[i] = lf_s[lq * 8 + i][kc + kk];
            #pragma unroll
            for (int i = 0; i < 8; i++)
                #pragma unroll
                for (int jj = 0; jj < 4; jj++) acc[i][jj] += lv[i] * wv[jj];
        }
    }
    float* dst = g_Pp + (size_t)blockIdx.y * NLAB * HID;
    #pragma unroll
    for (int i = 0; i < 8; i++)
        #pragma unroll
        for (int jj = 0; jj < 4; jj++)
            dst[(size_t)(lq * 8 + i) * HID + j0 + jq + 32 * jj] = acc[i][jj];
}

__global__ void p_reduce_kernel(const float* __restrict__ merge_b) {
    int i = blockIdx.x * blockDim.x + threadIdx.x;
    if (i >= NLAB * HID) return;
    float s = merge_b[i % HID];
    #pragma unroll
    for (int t = 0; t < KT_SPLITS; t++) s += g_Pp[t * NLAB * HID + i];
    g_P[i] = s;
}

// ---------------------------------------------------------------------------
// Main kernel: 128(M) x 256(N) tiles, K=768 in 12 chunks of BK=64.
//  USE_TC: tcgen05, A = LDG f32 + split + STS; B = cp.async.cg from g_Bh/g_Bl.
//          2-stage pipeline (96KB/stage), MMA issuer warp, TMEM epilogue.
//  else:   TF32 mma.sync fallback (two 128-col halves sequentially).
// ---------------------------------------------------------------------------
#define STG_SZ 98304                  // Ah16K|Al16K|Bh32K|Bl32K
#define OFF_AH(s) (1024 + (s) * STG_SZ)
#define OFF_AL(s) (OFF_AH(s) + 16384)
#define OFF_BH(s) (OFF_AH(s) + 32768)
#define OFF_BL(s) (OFF_AH(s) + 65536)
#define SMEM_TOTAL (1024 + 2 * STG_SZ)
#define MB_FULL(s)  (sb + 16 + (s) * 8)
#define MB_EMPTY(s) (sb + 32 + (s) * 8)
#define MB_DONE     (sb + 48)

__global__ __launch_bounds__(288, 1)
void fm_main_kernel(const float* __restrict__ tokens,
                    const int* __restrict__ labels,
                    const float* __restrict__ W,
                    float* __restrict__ out) {
    extern __shared__ char smem[];
    const int tid = threadIdx.x, wid = tid >> 5, lane = tid & 31;
    const int m0 = blockIdx.y * 128;

#if USE_TC
    const int n0 = blockIdx.x * 256;
    const uint32_t sb = smem_u32(smem);
    int* lbl_s = (int*)(smem + 512);
    if (tid < 128) lbl_s[tid] = labels[m0 + tid];
    if (tid == 0) {
        MBAR_INIT(MB_FULL(0), 256); MBAR_INIT(MB_FULL(1), 256);
        MBAR_INIT(MB_EMPTY(0), 1);  MBAR_INIT(MB_EMPTY(1), 1);
        MBAR_INIT(MB_DONE, 1);
    }
    if (wid == 8) { TC_ALLOC(sb, 256); TC_RELINQ(); }
    __syncthreads();
    uint32_t tmem;
    asm volatile("ld.shared.b32 %0, [%1];" : "=r"(tmem) : "r"(sb));

    if (wid == 8) {
        // ---- MMA issuer warp: 4 K-steps x 3 split terms, N=256 ----
        for (int c = 0; c < 12; c++) {
            const int s = c & 1;
            MBAR_WAIT(MB_FULL(s), (c >> 1) & 1);
            if (elect_one()) {
                uint64_t ah = MK_DESC(sb + OFF_AH(s)), al = MK_DESC(sb + OFF_AL(s));
                uint64_t bh = MK_DESC(sb + OFF_BH(s)), bl = MK_DESC(sb + OFF_BL(s));
                #pragma unroll
                for (int ks = 0; ks < 4; ks++) {
                    mma_bf16_ss(tmem, ah + 2 * ks, bh + 2 * ks, (c | ks) ? 1u : 0u);
                    mma_bf16_ss(tmem, ah + 2 * ks, bl + 2 * ks, 1u);
                    mma_bf16_ss(tmem, al + 2 * ks, bh + 2 * ks, 1u);
                }
                TC_COMMIT(MB_EMPTY(s));
                if (c == 11) TC_COMMIT(MB_DONE);
            }
        }
    } else {
        // ---- producers (256 threads) ----
        // A: thread handles half-row (32 k) -> LDG f32, split, STS hi/lo.
        const int ar = tid >> 1, kh = (tid & 1) * 32;
        const float* arow = tokens + (size_t)(m0 + ar) * HID + kh;
        uint32_t aswo[4];
        #pragma unroll
        for (int u = 0; u < 4; u++) aswo[u] = SW128((uint32_t)(ar * 128 + (kh + 8 * u) * 2));
        // B: thread handles one n-row (128B hi + 128B lo) via cp.async.
        const __nv_bfloat16* bhrow = g_Bh + (size_t)(n0 + tid) * HID;
        const __nv_bfloat16* blrow = g_Bl + (size_t)(n0 + tid) * HID;
        uint32_t bswo[8];
        #pragma unroll
        for (int u = 0; u < 8; u++) bswo[u] = SW128((uint32_t)(tid * 128 + u * 16));

        for (int c = 0; c < 12; c++) {
            const int s = c & 1, k0 = c * 64;
            if (c >= 2) MBAR_WAIT(MB_EMPTY(s), ((c >> 1) - 1) & 1);
            // B first (async engine runs while we convert A)
            #pragma unroll
            for (int u = 0; u < 8; u++) {
                CP_ASYNC16(sb + OFF_BH(s) + bswo[u], (const char*)(bhrow + k0) + 16 * u);
                CP_ASYNC16(sb + OFF_BL(s) + bswo[u], (const char*)(blrow + k0) + 16 * u);
            }
            CP_COMMIT();
            // A: load f32, hi/lo split, swizzled STS
            uint32_t h[16], l[16];
            #pragma unroll
            for (int i = 0; i < 8; i++) {
                float4 v = *(const float4*)(arow + k0 + 4 * i);
                __nv_bfloat16 hx = __float2bfloat16(v.x), hy = __float2bfloat16(v.y);
                __nv_bfloat16 hz = __float2bfloat16(v.z), hw = __float2bfloat16(v.w);
                __nv_bfloat162 p0 = {hx, hy}, p1 = {hz, hw};
                h[2 * i] = *(uint32_t*)&p0; h[2 * i + 1] = *(uint32_t*)&p1;
                __nv_bfloat162 q0 = {__float2bfloat16(v.x - __bfloat162float(hx)),
                                     __float2bfloat16(v.y - __bfloat162float(hy))};
                __nv_bfloat162 q1 = {__float2bfloat16(v.z - __bfloat162float(hz)),
                                     __float2bfloat16(v.w - __bfloat162float(hw))};
                l[2 * i] = *(uint32_t*)&q0; l[2 * i + 1] = *(uint32_t*)&q1;
            }
            #pragma unroll
            for (int u = 0; u < 4; u++) {
                *(uint4*)(smem + OFF_AH(s) + aswo[u]) =
                    make_uint4(h[4*u], h[4*u+1], h[4*u+2], h[4*u+3]);
                *(uint4*)(smem + OFF_AL(s) + aswo[u]) =
                    make_uint4(l[4*u], l[4*u+1], l[4*u+2], l[4*u+3]);
            }
            CP_WAIT0();
            FENCE_ASYNC();
            MBAR_ARRIVE(MB_FULL(s));
        }
    }

    // ---- epilogue: TMEM -> SMEM transpose -> coalesced STG, 4 slabs of 64 ----
    MBAR_WAIT(MB_DONE, 0);
    TC_FENCE_AFTER();
    float* eps = (float*)(smem + 1024);          // [128][68] (aliases stages)
    #pragma unroll
    for (int h = 0; h < 4; h++) {
        if (wid < 4) {
            uint32_t d[64];
            LDTM_X32(d, tmem + h * 64);
            LDTM_X32(d + 32, tmem + h * 64 + 32);
            TC_WAIT_LD();
            const int row = wid * 32 + lane;
            #pragma unroll
            for (int cc = 0; cc < 64; cc++) eps[row * 68 + cc] = __uint_as_float(d[cc]);
        }
        __syncthreads();
        if (tid < 256) {
            const int r = tid >> 1, cb = (tid & 1) * 32;
            const int lbl = lbl_s[r];
            const size_t ro = (size_t)(m0 + r) * HID + n0 + h * 64 + cb;
            if (lbl) {
                const float* prow = g_P + (size_t)(lbl - 1) * HID + n0 + h * 64 + cb;
                #pragma unroll
                for (int q = 0; q < 8; q++) {
                    float4 o;
                    o.x = eps[r * 68 + cb + 4*q + 0] + prow[4*q + 0];
                    o.y = eps[r * 68 + cb + 4*q + 1] + prow[4*q + 1];
                    o.z = eps[r * 68 + cb + 4*q + 2] + prow[4*q + 2];
                    o.w = eps[r * 68 + cb + 4*q + 3] + prow[4*q + 3];
                    *(float4*)(out + ro + 4*q) = o;
                }
            } else {
                #pragma unroll
                for (int q = 0; q < 8; q++)
                    *(float4*)(out + ro + 4*q) = *(const float4*)(tokens + ro + 4*q);
            }
        }
        __syncthreads();
    }
    if (wid == 8) TC_DEALLOC(tmem, 256);

#else  // ------------------- portable TF32 mma.sync fallback -------------------
    float (*As)[36] = (float(*)[36])(smem);                  // [128][36]
    float (*Bs)[36] = (float(*)[36])(smem + 128 * 36 * 4);   // [128][36]
    int*   lbl_s    = (int*)(smem + 2 * 128 * 36 * 4);

    if (tid < 128) lbl_s[tid] = labels[m0 + tid];

    const int wm = wid >> 2, wn = wid & 3;   // valid for wid<8 only
    for (int nh = 0; nh < 2; nh++) {
        const int n0 = blockIdx.x * 256 + nh * 128;
        float acc[4][4][4];
        #pragma unroll
        for (int a = 0; a < 4; a++)
            #pragma unroll
            for (int b = 0; b < 4; b++)
                #pragma unroll
                for (int c = 0; c < 4; c++) acc[a][b][c] = 0.f;
        __syncthreads();

        for (int k0 = 0; k0 < HID; k0 += 32) {
            if (tid < 256) {
                #pragma unroll
                for (int i = 0; i < 4; i++) {
                    int idx = tid + i * 256;
                    int r = idx >> 3, c = (idx & 7) * 4;
                    float4 va = *(const float4*)(tokens + (size_t)(m0 + r) * HID + k0 + c);
                    va.x = to_tf32(va.x); va.y = to_tf32(va.y);
                    va.z = to_tf32(va.z); va.w = to_tf32(va.w);
                    *(float4*)&As[r][c] = va;
                    float4 vb = *(const float4*)(W + (size_t)(n0 + r) * HID2 + k0 + c);
                    vb.x = to_tf32(vb.x); vb.y = to_tf32(vb.y);
                    vb.z = to_tf32(vb.z); vb.w = to_tf32(vb.w);
                    *(float4*)&Bs[r][c] = vb;
                }
            }
            __syncthreads();
            if (tid < 256) {
                #pragma unroll
                for (int ks = 0; ks < 4; ks++) {
                    const int cb = ks * 8 + (lane & 3);
                    float a[4][4], b[4][2];
                    #pragma unroll
                    for (int mi = 0; mi < 4; mi++) {
                        int r = wm * 64 + mi * 16 + (lane >> 2);
                        a[mi][0] = As[r][cb];     a[mi][1] = As[r + 8][cb];
                        a[mi][2] = As[r][cb + 4]; a[mi][3] = As[r + 8][cb + 4];
                    }
                    #pragma unroll
                    for (int ni = 0; ni < 4; ni++) {
                        int r = wn * 32 + ni * 8 + (lane >> 2);
                        b[ni][0] = Bs[r][cb]; b[ni][1] = Bs[r][cb + 4];
                    }
                    #pragma unroll
                    for (int mi = 0; mi < 4; mi++)
                        #pragma unroll
                        for (int ni = 0; ni < 4; ni++)
                            mma_tf32(acc[mi][ni], a[mi], b[ni]);
                }
            }
            __syncthreads();
        }

        if (tid < 256) {
            const int gq = lane >> 2, tg = lane & 3;
            #pragma unroll
            for (int mi = 0; mi < 4; mi++) {
                #pragma unroll
                for (int half = 0; half < 2; half++) {
                    int r = wm * 64 + mi * 16 + gq + half * 8;
                    int lbl = lbl_s[r];
                    size_t rowOff = (size_t)(m0 + r) * HID;
                    #pragma unroll
                    for (int ni = 0; ni < 4; ni++) {
                        int gc = n0 + wn * 32 + ni * 8 + tg * 2;
                        float2 res;
                        if (lbl != 0) {
                            float2 p = *(const float2*)(&g_P[(size_t)(lbl - 1) * HID + gc]);
                            res.x = acc[mi][ni][half * 2 + 0] + p.x;
                            res.y = acc[mi][ni][half * 2 + 1] + p.y;
                        } else {
                            res = *(const float2*)(tokens + rowOff + gc);
                        }
                        *(float2*)(out + rowOff + gc) = res;
                    }
                }
            }
        }
    }
#endif
}

extern "C" void kernel_launch(void* const* d_in, const int* in_sizes, int n_in,
                              void* d_out, int out_size) {
    const float* com    = (const float*)d_in[0];   // [16,4096,768] f32
    const int*   labels = (const int*)d_in[1];     // [16,4096] int32
    const float* lf     = (const float*)d_in[2];   // [64,768] f32
    const float* mw     = (const float*)d_in[3];   // [768,1536] f32
    const float* mb     = (const float*)d_in[4];   // [768] f32
    float* out = (float*)d_out;

    cudaFuncSetAttribute(fm_main_kernel,
                         cudaFuncAttributeMaxDynamicSharedMemorySize, SMEM_TOTAL);

    bsplit_kernel<<<576, 256>>>(mw);
    p_accum_kernel<<<dim3(6, KT_SPLITS), 256>>>(lf, mw);
    p_reduce_kernel<<<(NLAB * HID + 255) / 256, 256>>>(mb);
    fm_main_kernel<<<dim3(3, NTOK / 128), 288, SMEM_TOTAL>>>(com, labels, mw, out);
}

// round 12
// speedup vs baseline: 1.6787x; 1.0185x over previous
#include <cuda_runtime.h>
#include <cuda_bf16.h>
#include <cstdint>
#include <cstddef>

#define HID   768
#define HID2  1536
#define NLAB  64
#define NTOK  65536
#define NTILES 1536            // 512 m-tiles x 3 n-tiles
#define KT_SPLITS 12

#if defined(__CUDA_ARCH__) && (defined(__CUDA_ARCH_FEAT_SM103_ALL) || \
    defined(__CUDA_ARCH_FEAT_SM100_ALL) || defined(__CUDA_ARCH_SPECIFIC__))
#define USE_TC 1
#else
#define USE_TC 0
#endif

// ---------------- scratch ----------------
__device__ __align__(16) float g_P[NLAB * HID];
__device__ __align__(16) float g_Pp[KT_SPLITS * NLAB * HID];
__device__ __align__(16) __nv_bfloat16 g_Bh[HID * HID];
__device__ __align__(16) __nv_bfloat16 g_Bl[HID * HID];

// ---------------- portable helpers ----------------
__device__ __forceinline__ uint32_t smem_u32(const void* p) {
    uint32_t a;
    asm("{ .reg .u64 t; cvta.to.shared.u64 t, %1; cvt.u32.u64 %0, t; }" : "=r"(a) : "l"(p));
    return a;
}
__device__ __forceinline__ float to_tf32(float x) {
    uint32_t u;
    asm("cvt.rna.tf32.f32 %0, %1;" : "=r"(u) : "f"(x));
    return __uint_as_float(u);
}
__device__ __forceinline__ void mma_tf32(float d[4], const float a[4], const float b[2]) {
    asm volatile(
        "mma.sync.aligned.m16n8k8.row.col.f32.tf32.tf32.f32 "
        "{%0,%1,%2,%3}, {%4,%5,%6,%7}, {%8,%9}, {%0,%1,%2,%3};\n"
        : "+f"(d[0]), "+f"(d[1]), "+f"(d[2]), "+f"(d[3])
        : "r"(__float_as_uint(a[0])), "r"(__float_as_uint(a[1])),
          "r"(__float_as_uint(a[2])), "r"(__float_as_uint(a[3])),
          "r"(__float_as_uint(b[0])), "r"(__float_as_uint(b[1])));
}
__device__ __forceinline__ void split4(float4 v, uint2& h, uint2& l) {
    __nv_bfloat16 hx = __float2bfloat16(v.x), hy = __float2bfloat16(v.y);
    __nv_bfloat16 hz = __float2bfloat16(v.z), hw = __float2bfloat16(v.w);
    __nv_bfloat162 p0 = {hx, hy}, p1 = {hz, hw};
    h.x = *(uint32_t*)&p0; h.y = *(uint32_t*)&p1;
    __nv_bfloat162 q0 = {__float2bfloat16(v.x - __bfloat162float(hx)),
                         __float2bfloat16(v.y - __bfloat162float(hy))};
    __nv_bfloat162 q1 = {__float2bfloat16(v.z - __bfloat162float(hz)),
                         __float2bfloat16(v.w - __bfloat162float(hw))};
    l.x = *(uint32_t*)&q0; l.y = *(uint32_t*)&q1;
}

#define SW128(o) ((o) ^ (((o) >> 3) & 0x70))
#define CP_ASYNC16(dst, src) \
    asm volatile("cp.async.cg.shared.global [%0], [%1], 16;" :: "r"(dst), "l"(src) : "memory")
#define CP_COMMIT() asm volatile("cp.async.commit_group;" ::: "memory")
#define CP_WAIT0()  asm volatile("cp.async.wait_group 0;" ::: "memory")

// ---------------- sm_103a-specific ----------------
#if USE_TC
__device__ __forceinline__ uint32_t elect_one() {
    uint32_t p;
    asm volatile("{ .reg .pred p; elect.sync _|p, 0xFFFFFFFF; selp.b32 %0, 1, 0, p; }" : "=r"(p));
    return p;
}
#define MBAR_INIT(a, n)  asm volatile("mbarrier.init.shared.b64 [%0], %1;" :: "r"(a), "r"((uint32_t)(n)) : "memory")
#define MBAR_ARRIVE(a)   asm volatile("mbarrier.arrive.shared.b64 _, [%0];" :: "r"(a) : "memory")
#define MBAR_WAIT(a, ph) do {                                                      \
    uint32_t _m = (a), _p = (ph), _d;                                              \
    asm volatile("{ .reg .pred p; mbarrier.try_wait.parity.acquire.cta.shared::cta.b64 p, [%1], %2; selp.b32 %0,1,0,p; }" \
        : "=r"(_d) : "r"(_m), "r"(_p) : "memory");                                 \
    if (!_d) {                                                                     \
        asm volatile("{ .reg .pred P1; WL_%=: mbarrier.try_wait.parity.acquire.cta.shared::cta.b64 P1, [%0], %1, 0x989680;" \
                     " @P1 bra.uni WD_%=; bra.uni WL_%=; WD_%=: }"                 \
                     :: "r"(_m), "r"(_p) : "memory");                              \
    } } while (0)
#define TC_ALLOC(sa, n)   asm volatile("tcgen05.alloc.cta_group::1.sync.aligned.shared::cta.b32 [%0], %1;" :: "r"(sa), "r"((uint32_t)(n)) : "memory")
#define TC_DEALLOC(t, n)  asm volatile("tcgen05.dealloc.cta_group::1.sync.aligned.b32 %0, %1;" :: "r"(t), "r"((uint32_t)(n)))
#define TC_RELINQ()       asm volatile("tcgen05.relinquish_alloc_permit.cta_group::1.sync.aligned;")
#define TC_COMMIT(a)      asm volatile("tcgen05.commit.cta_group::1.mbarrier::arrive::one.shared::cluster.b64 [%0];" :: "r"(a) : "memory")
#define TC_WAIT_LD()      asm volatile("tcgen05.wait::ld.sync.aligned;" ::: "memory")
#define TC_FENCE_AFTER()  asm volatile("tcgen05.fence::after_thread_sync;" ::: "memory")
#define FENCE_ASYNC()     asm volatile("fence.proxy.async.shared::cta;" ::: "memory")
#define BAR_PROD()        asm volatile("bar.sync 1, 256;" ::: "memory")
#define LDTM_X32(r, t) \
    asm volatile("tcgen05.ld.sync.aligned.32x32b.x32.b32 " \
        "{%0,%1,%2,%3,%4,%5,%6,%7,%8,%9,%10,%11,%12,%13,%14,%15," \
        "%16,%17,%18,%19,%20,%21,%22,%23,%24,%25,%26,%27,%28,%29,%30,%31}, [%32];" \
        : "=r"((r)[0]),"=r"((r)[1]),"=r"((r)[2]),"=r"((r)[3]),"=r"((r)[4]),"=r"((r)[5]),"=r"((r)[6]),"=r"((r)[7]), \
          "=r"((r)[8]),"=r"((r)[9]),"=r"((r)[10]),"=r"((r)[11]),"=r"((r)[12]),"=r"((r)[13]),"=r"((r)[14]),"=r"((r)[15]), \
          "=r"((r)[16]),"=r"((r)[17]),"=r"((r)[18]),"=r"((r)[19]),"=r"((r)[20]),"=r"((r)[21]),"=r"((r)[22]),"=r"((r)[23]), \
          "=r"((r)[24]),"=r"((r)[25]),"=r"((r)[26]),"=r"((r)[27]),"=r"((r)[28]),"=r"((r)[29]),"=r"((r)[30]),"=r"((r)[31]) \
        : "r"(t))

static constexpr uint64_t DESC_BASE_SW128 =
    (uint64_t(2) << 61) | (uint64_t(1) << 46) | (uint64_t(64) << 32) | (uint64_t(1) << 16);
#define MK_DESC(a) (DESC_BASE_SW128 | ((uint64_t)((a) >> 4) & 0x3FFF))

static constexpr uint32_t IDESC_128x256 =
    (1u << 4) | (1u << 7) | (1u << 10) | ((256u / 8) << 17) | ((128u / 16) << 24);

__device__ __forceinline__ void mma_bf16_ss(uint32_t d_tmem, uint64_t a_desc,
                                            uint64_t b_desc, uint32_t en) {
    asm volatile(
        "{ .reg .pred p; setp.ne.u32 p, %4, 0;"
        " tcgen05.mma.cta_group::1.kind::f16 [%0], %1, %2, %3, {%5,%5,%5,%5}, p; }"
        :: "r"(d_tmem), "l"(a_desc), "l"(b_desc), "r"(IDESC_128x256),
           "r"(en), "r"(0u) : "memory");
}
#endif // USE_TC

// ---------------- prep kernels (unchanged) ----------------
__global__ void bsplit_kernel(const float* __restrict__ W) {
    int n = blockIdx.x * 256 + threadIdx.x;
    int j = n / 192, k4 = (n % 192) * 4;
    float4 v = *(const float4*)(W + (size_t)j * HID2 + k4);
    uint2 h, l;
    split4(v, h, l);
    size_t o = (size_t)j * HID + k4;
    *(uint2*)(g_Bh + o) = h;
    *(uint2*)(g_Bl + o) = l;
}

__global__ __launch_bounds__(256) void p_accum_kernel(
        const float* __restrict__ lf, const float* __restrict__ W) {
    __shared__ float lf_s[64][64];
    __shared__ float w_s[128][33];
    const int tid = threadIdx.x;
    const int j0 = blockIdx.x * 128, k0 = blockIdx.y * 64;
    #pragma unroll
    for (int i = 0; i < 4; i++) {
        int idx = tid + i * 256, r = idx >> 4, c = (idx & 15) * 4;
        *(float4*)&lf_s[r][c] = *(const float4*)(lf + (size_t)r * HID + k0 + c);
    }
    const int jq = tid & 31, lq = tid >> 5;
    float acc[8][4];
    #pragma unroll
    for (int i = 0; i < 8; i++)
        #pragma unroll
        for (int jj = 0; jj < 4; jj++) acc[i][jj] = 0.f;
    for (int kc = 0; kc < 64; kc += 32) {
        __syncthreads();
        #pragma unroll
        for (int i = 0; i < 4; i++) {
            int idx = tid + i * 256, r = idx >> 3, c = (idx & 7) * 4;
            const float* src = W + (size_t)(j0 + r) * HID2 + HID + k0 + kc + c;
            w_s[r][c] = src[0]; w_s[r][c+1] = src[1]; w_s[r][c+2] = src[2]; w_s[r][c+3] = src[3];
        }
        __syncthreads();
        #pragma unroll
        for (int kk = 0; kk < 32; kk++) {
            float wv[4], lv[8];
            #pragma unroll
            for (int jj = 0; jj < 4; jj++) wv[jj] = w_s[jq + 32 * jj][kk];
            #pragma unroll
            for (int i = 0; i < 8; i++) lv[i] = lf_s[lq * 8 + i][kc + kk];
            #pragma unroll
            for (int i = 0; i < 8; i++)
                #pragma unroll
                for (int jj = 0; jj < 4; jj++) acc[i][jj] += lv[i] * wv[jj];
        }
    }
    float* dst = g_Pp + (size_t)blockIdx.y * NLAB * HID;
    #pragma unroll
    for (int i = 0; i < 8; i++)
        #pragma unroll
        for (int jj = 0; jj < 4; jj++)
            dst[(size_t)(lq * 8 + i) * HID + j0 + jq + 32 * jj] = acc[i][jj];
}

__global__ void p_reduce_kernel(const float* __restrict__ merge_b) {
    int i = blockIdx.x * blockDim.x + threadIdx.x;
    if (i >= NLAB * HID) return;
    float s = merge_b[i % HID];
    #pragma unroll
    for (int t = 0; t < KT_SPLITS; t++) s += g_Pp[t * NLAB * HID + i];
    g_P[i] = s;
}

// ---------------------------------------------------------------------------
// Persistent main kernel. 148 CTAs x 288 threads.
// TC path: tile = 128(M) x 256(N), K=768 in 12 chunks of BK=64.
//   TMEM double-buffer (2x256 cols): epilogue of tile t-1 (producer warps)
//   overlaps MMAs of tile t (issuer warp). Coalesced A loads (nL=4).
// ---------------------------------------------------------------------------
#define STG_SZ 98304                  // Ah16K|Al16K|Bh32K|Bl32K
#define OFF_AH(s) (1024 + (s) * STG_SZ)
#define OFF_AL(s) (OFF_AH(s) + 16384)
#define OFF_BH(s) (OFF_AH(s) + 32768)
#define OFF_BL(s) (OFF_AH(s) + 65536)
#define EPS_OFF   (1024 + 2 * STG_SZ)            // 128 x 66 floats = 33792 B
#define SMEM_TOTAL (EPS_OFF + 128 * 66 * 4)      // 231424 B
#define MB_FULL(s)  (sb + 16 + (s) * 8)
#define MB_EMPTY(s) (sb + 32 + (s) * 8)
#define MB_DONE(p)  (sb + 48 + (p) * 8)
#define MB_EFREE(p) (sb + 64 + (p) * 8)

__global__ __launch_bounds__(288, 1)
void fm_main_kernel(const float* __restrict__ tokens,
                    const int* __restrict__ labels,
                    const float* __restrict__ W,
                    float* __restrict__ out) {
    extern __shared__ char smem[];
    const int tid = threadIdx.x, wid = tid >> 5, lane = tid & 31;
    const int bid = blockIdx.x;

#if USE_TC
    const uint32_t sb = smem_u32(smem);
    if (tid == 0) {
        MBAR_INIT(MB_FULL(0), 256);  MBAR_INIT(MB_FULL(1), 256);
        MBAR_INIT(MB_EMPTY(0), 1);   MBAR_INIT(MB_EMPTY(1), 1);
        MBAR_INIT(MB_DONE(0), 1);    MBAR_INIT(MB_DONE(1), 1);
        MBAR_INIT(MB_EFREE(0), 256); MBAR_INIT(MB_EFREE(1), 256);
    }
    if (wid == 8) { TC_ALLOC(sb, 512); TC_RELINQ(); }
    __syncthreads();
    uint32_t tmem;
    asm volatile("ld.shared.b32 %0, [%1];" : "=r"(tmem) : "r"(sb));

    if (wid == 8) {
        // =============== MMA issuer warp ===============
        int cc = 0;
        for (int it = 0; ; it++) {
            const int t = bid + it * 148;
            if (t >= NTILES) break;
            const uint32_t dtm = tmem + (it & 1) * 256;
            if (it >= 2) {
                MBAR_WAIT(MB_EFREE(it & 1), ((it >> 1) - 1) & 1);
                TC_FENCE_AFTER();
            }
            for (int c = 0; c < 12; c++, cc++) {
                const int s = cc & 1;
                MBAR_WAIT(MB_FULL(s), (cc >> 1) & 1);
                if (elect_one()) {
                    uint64_t ah = MK_DESC(sb + OFF_AH(s)), al = MK_DESC(sb + OFF_AL(s));
                    uint64_t bh = MK_DESC(sb + OFF_BH(s)), bl = MK_DESC(sb + OFF_BL(s));
                    #pragma unroll
                    for (int ks = 0; ks < 4; ks++) {
                        mma_bf16_ss(dtm, ah + 2 * ks, bh + 2 * ks, (c | ks) ? 1u : 0u);
                        mma_bf16_ss(dtm, ah + 2 * ks, bl + 2 * ks, 1u);
                        mma_bf16_ss(dtm, al + 2 * ks, bh + 2 * ks, 1u);
                    }
                    TC_COMMIT(MB_EMPTY(s));
                    if (c == 11) TC_COMMIT(MB_DONE(it & 1));
                }
            }
        }
    } else {
        // =============== producers + epilogue (256 threads) ===============
        const int q = lane & 7, rsub = lane >> 3;          // A: 8 lanes/row, 4 rows/warp/pass
        uint32_t aoff[4][2], boff[8];
        #pragma unroll
        for (int p = 0; p < 4; p++) {
            const int row = p * 32 + wid * 4 + rsub;
            aoff[p][0] = SW128((uint32_t)(row * 128 + q * 8));
            aoff[p][1] = SW128((uint32_t)(row * 128 + 64 + q * 8));
        }
        #pragma unroll
        for (int u = 0; u < 8; u++) boff[u] = SW128((uint32_t)(tid * 128 + u * 16));
        float* eps = (float*)(smem + EPS_OFF);

        int cc = 0;
        for (int it = 0; ; it++) {
            const int t = bid + it * 148;
            const bool have = t < NTILES;
            if (have) {
                const int m0 = (t / 3) * 128, n0 = (t % 3) * 256;
                const float* abase = tokens + (size_t)m0 * HID + q * 4;
                const __nv_bfloat16* bhrow = g_Bh + (size_t)(n0 + tid) * HID;
                const __nv_bfloat16* blrow = g_Bl + (size_t)(n0 + tid) * HID;
                for (int c = 0; c < 12; c++, cc++) {
                    const int s = cc & 1, k0 = c * 64;
                    // A: coalesced loads (4 rows x 128B per warp-LDG) + split, pre-wait
                    uint2 h[4][2], l[4][2];
                    #pragma unroll
                    for (int p = 0; p < 4; p++) {
                        const float* rp = abase + (size_t)(p * 32 + wid * 4 + rsub) * HID + k0;
                        float4 v0 = *(const float4*)rp;
                        float4 v1 = *(const float4*)(rp + 32);
                        split4(v0, h[p][0], l[p][0]);
                        split4(v1, h[p][1], l[p][1]);
                    }
                    if (cc >= 2) MBAR_WAIT(MB_EMPTY(s), ((cc >> 1) - 1) & 1);
                    #pragma unroll
                    for (int u = 0; u < 8; u++) {
                        CP_ASYNC16(sb + OFF_BH(s) + boff[u], (const char*)(bhrow + k0) + 16 * u);
                        CP_ASYNC16(sb + OFF_BL(s) + boff[u], (const char*)(blrow + k0) + 16 * u);
                    }
                    CP_COMMIT();
                    #pragma unroll
                    for (int p = 0; p < 4; p++) {
                        *(uint2*)(smem + OFF_AH(s) + aoff[p][0]) = h[p][0];
                        *(uint2*)(smem + OFF_AH(s) + aoff[p][1]) = h[p][1];
                        *(uint2*)(smem + OFF_AL(s) + aoff[p][0]) = l[p][0];
                        *(uint2*)(smem + OFF_AL(s) + aoff[p][1]) = l[p][1];
                    }
                    CP_WAIT0();
                    FENCE_ASYNC();
                    MBAR_ARRIVE(MB_FULL(s));
                }
            }
            // ---- epilogue of tile it-1 (overlaps issuer's MMAs of tile it) ----
            if (it >= 1) {
                const int tp = bid + (it - 1) * 148;
                const int pm0 = (tp / 3) * 128, pn0 = (tp % 3) * 256;
                const int pb = (it - 1) & 1;
                MBAR_WAIT(MB_DONE(pb), ((it - 1) >> 1) & 1);
                TC_FENCE_AFTER();
                const uint32_t dtm = tmem + pb * 256;
                const int r = tid >> 1, cb = (tid & 1) * 32;
                const int lbl = labels[pm0 + r];
                #pragma unroll
                for (int hh = 0; hh < 4; hh++) {
                    if (wid < 4) {
                        uint32_t d[64];
                        LDTM_X32(d, dtm + hh * 64);
                        LDTM_X32(d + 32, dtm + hh * 64 + 32);
                        TC_WAIT_LD();
                        float* er = eps + (wid * 32 + lane) * 66;
                        #pragma unroll
                        for (int j = 0; j < 32; j++)
                            *(uint2*)(er + 2 * j) = make_uint2(d[2 * j], d[2 * j + 1]);
                    }
                    BAR_PROD();
                    const float* er = eps + r * 66 + cb;
                    const size_t ro = (size_t)(pm0 + r) * HID + pn0 + hh * 64 + cb;
                    if (lbl) {
                        const float* prow = g_P + (size_t)(lbl - 1) * HID + pn0 + hh * 64 + cb;
                        #pragma unroll
                        for (int g = 0; g < 8; g++) {
                            float2 a = *(const float2*)(er + 4 * g);
                            float2 b = *(const float2*)(er + 4 * g + 2);
                            float4 pv = *(const float4*)(prow + 4 * g);
                            float4 o = {a.x + pv.x, a.y + pv.y, b.x + pv.z, b.y + pv.w};
                            *(float4*)(out + ro + 4 * g) = o;
                        }
                    } else {
                        #pragma unroll
                        for (int g = 0; g < 8; g++)
                            *(float4*)(out + ro + 4 * g) = *(const float4*)(tokens + ro + 4 * g);
                    }
                    BAR_PROD();
                }
                MBAR_ARRIVE(MB_EFREE(pb));
            }
            if (!have) break;
        }
    }
    __syncthreads();
    if (wid == 8) TC_DEALLOC(tmem, 512);

#else  // ------------------- portable TF32 fallback (persistent) -------------------
    float (*As)[36] = (float(*)[36])(smem);
    float (*Bs)[36] = (float(*)[36])(smem + 128 * 36 * 4);
    int*   lbl_s    = (int*)(smem + 2 * 128 * 36 * 4);
    const int wm = wid >> 2, wn = wid & 3;

    for (int it = 0; ; it++) {
        const int t = bid + it * 148;
        if (t >= NTILES) break;
        const int m0 = (t / 3) * 128, base_n = (t % 3) * 256;
        __syncthreads();
        if (tid < 128) lbl_s[tid] = labels[m0 + tid];

        for (int nh = 0; nh < 2; nh++) {
            const int n0 = base_n + nh * 128;
            float acc[4][4][4];
            #pragma unroll
            for (int a = 0; a < 4; a++)
                #pragma unroll
                for (int b = 0; b < 4; b++)
                    #pragma unroll
                    for (int c = 0; c < 4; c++) acc[a][b][c] = 0.f;
            __syncthreads();

            for (int k0 = 0; k0 < HID; k0 += 32) {
                if (tid < 256) {
                    #pragma unroll
                    for (int i = 0; i < 4; i++) {
                        int idx = tid + i * 256;
                        int r = idx >> 3, c = (idx & 7) * 4;
                        float4 va = *(const float4*)(tokens + (size_t)(m0 + r) * HID + k0 + c);
                        va.x = to_tf32(va.x); va.y = to_tf32(va.y);
                        va.z = to_tf32(va.z); va.w = to_tf32(va.w);
                        *(float4*)&As[r][c] = va;
                        float4 vb = *(const float4*)(W + (size_t)(n0 + r) * HID2 + k0 + c);
                        vb.x = to_tf32(vb.x); vb.y = to_tf32(vb.y);
                        vb.z = to_tf32(vb.z); vb.w = to_tf32(vb.w);
                        *(float4*)&Bs[r][c] = vb;
                    }
                }
                __syncthreads();
                if (tid < 256) {
                    #pragma unroll
                    for (int ks = 0; ks < 4; ks++) {
                        const int cb = ks * 8 + (lane & 3);
                        float a[4][4], b[4][2];
                        #pragma unroll
                        for (int mi = 0; mi < 4; mi++) {
                            int r = wm * 64 + mi * 16 + (lane >> 2);
                            a[mi][0] = As[r][cb];     a[mi][1] = As[r + 8][cb];
                            a[mi][2] = As[r][cb + 4]; a[mi][3] = As[r + 8][cb + 4];
                        }
                        #pragma unroll
                        for (int ni = 0; ni < 4; ni++) {
                            int r = wn * 32 + ni * 8 + (lane >> 2);
                            b[ni][0] = Bs[r][cb]; b[ni][1] = Bs[r][cb + 4];
                        }
                        #pragma unroll
                        for (int mi = 0; mi < 4; mi++)
                            #pragma unroll
                            for (int ni = 0; ni < 4; ni++)
                                mma_tf32(acc[mi][ni], a[mi], b[ni]);
                    }
                }
                __syncthreads();
            }

            if (tid < 256) {
                const int gq = lane >> 2, tg = lane & 3;
                #pragma unroll
                for (int mi = 0; mi < 4; mi++) {
                    #pragma unroll
                    for (int half = 0; half < 2; half++) {
                        int r = wm * 64 + mi * 16 + gq + half * 8;
                        int lbl = lbl_s[r];
                        size_t rowOff = (size_t)(m0 + r) * HID;
                        #pragma unroll
                        for (int ni = 0; ni < 4; ni++) {
                            int gc = n0 + wn * 32 + ni * 8 + tg * 2;
                            float2 res;
                            if (lbl != 0) {
                                float2 p = *(const float2*)(&g_P[(size_t)(lbl - 1) * HID + gc]);
                                res.x = acc[mi][ni][half * 2 + 0] + p.x;
                                res.y = acc[mi][ni][half * 2 + 1] + p.y;
                            } else {
                                res = *(const float2*)(tokens + rowOff + gc);
                            }
                            *(float2*)(out + rowOff + gc) = res;
                        }
                    }
                }
            }
        }
    }
#endif
}

extern "C" void kernel_launch(void* const* d_in, const int* in_sizes, int n_in,
                              void* d_out, int out_size) {
    const float* com    = (const float*)d_in[0];   // [16,4096,768] f32
    const int*   labels = (const int*)d_in[1];     // [16,4096] int32
    const float* lf     = (const float*)d_in[2];   // [64,768] f32
    const float* mw     = (const float*)d_in[3];   // [768,1536] f32
    const float* mb     = (const float*)d_in[4];   // [768] f32
    float* out = (float*)d_out;

    cudaFuncSetAttribute(fm_main_kernel,
                         cudaFuncAttributeMaxDynamicSharedMemorySize, SMEM_TOTAL);

    bsplit_kernel<<<576, 256>>>(mw);
    p_accum_kernel<<<dim3(6, KT_SPLITS), 256>>>(lf, mw);
    p_reduce_kernel<<<(NLAB * HID + 255) / 256, 256>>>(mb);
    fm_main_kernel<<<148, 288, SMEM_TOTAL>>>(com, labels, mw, out);
}